// round 2
// baseline (speedup 1.0000x reference)
#include <cuda_runtime.h>
#include <cuda_bf16.h>
#include <math.h>

// ---------------- problem constants ----------------
#define BB 4
#define NN 2048
#define CC 256
#define KM 1024
#define KU 171            // ceil(2048/12)
#define HH 4
#define BK (BB*KU)        // 684

// ---------------- output layout (float32, tuple flattened) ----------------
#define SZ_A      ((long)BB*NN*KU)            // 1,400,832
#define OFF_SLOTS (SZ_A)
#define OFF_MUK   (OFF_SLOTS + (long)BK*CC)
#define OFF_SIGK  (OFF_MUK   + (long)BK*3)
#define OFF_IDX   (OFF_SIGK  + (long)BK*9)
#define OFF_SCAL  (OFF_IDX   + (long)BK)

// ---------------- scratch (device globals; allocation-free) ----------------
__device__ float g_ssum[BB*CC];
__device__ float g_initacc[BB*16];   // [0..8]=Sigma, [9..11]=mu, [12..14]=mu^2, [15]=mask
__device__ float g_q[BB*CC];
__device__ float g_mean[BB*3];
__device__ float g_std[BB*3];
__device__ float g_sigavg[BB*9];
__device__ float g_scores[BB*KM];
__device__ int   g_idx[BK];
__device__ float g_slots[BK*CC];
__device__ float g_muk[BK*3];
__device__ float g_sigk[BK*9];
__device__ float g_occ[BK];
__device__ float g_ksem[(long)BB*NN*CC];
__device__ float g_qsem[BK*CC];
__device__ float g_logits[(long)BB*NN*KU];
__device__ float g_At[(long)BK*NN];
__device__ float g_slotin[BK*CC];
__device__ float g_gi[BK*3*CC];
__device__ float g_gh[BK*3*CC];
__device__ float g_xm[BK*CC];
__device__ float g_t1[BK*4*CC];
__device__ float g_R[BB*KU*KU];
__device__ float g_gramn[BK];
__device__ float g_geo[2];
__device__ float g_red[8];

// ---------------- reduction helpers ----------------
__device__ __forceinline__ float warpSum(float v){
#pragma unroll
  for (int o=16;o;o>>=1) v += __shfl_xor_sync(0xffffffffu, v, o);
  return v;
}
__device__ __forceinline__ float warpMax(float v){
#pragma unroll
  for (int o=16;o;o>>=1) v = fmaxf(v, __shfl_xor_sync(0xffffffffu, v, o));
  return v;
}
__device__ __forceinline__ float blockReduceSum(float v, float* sh){
  int lane = threadIdx.x & 31, w = threadIdx.x >> 5;
  v = warpSum(v);
  if (lane==0) sh[w] = v;
  __syncthreads();
  int nw = (blockDim.x + 31) >> 5;
  float x = (threadIdx.x < nw) ? sh[threadIdx.x] : 0.f;
  if (w==0) x = warpSum(x);
  if (threadIdx.x==0) sh[0] = x;
  __syncthreads();
  float r = sh[0];
  __syncthreads();
  return r;
}
__device__ __forceinline__ float blockReduceMax(float v, float* sh){
  int lane = threadIdx.x & 31, w = threadIdx.x >> 5;
  v = warpMax(v);
  if (lane==0) sh[w] = v;
  __syncthreads();
  int nw = (blockDim.x + 31) >> 5;
  float x = (threadIdx.x < nw) ? sh[threadIdx.x] : -INFINITY;
  if (w==0) x = warpMax(x);
  if (threadIdx.x==0) sh[0] = x;
  __syncthreads();
  float r = sh[0];
  __syncthreads();
  return r;
}

// ---------------- zero ----------------
__global__ void zero_k(){
  int i = blockIdx.x*256 + threadIdx.x;
  if (i < BB*CC) g_ssum[i] = 0.f;
  if (i < BB*16) g_initacc[i] = 0.f;
  if (i < 8)     g_red[i] = 0.f;
}

// ---------------- init reductions over N ----------------
__global__ void reduce_init_k(const float* __restrict__ s, const float* __restrict__ mu,
                              const float* __restrict__ Sigma, const float* __restrict__ mask){
  int b = blockIdx.x, ch = blockIdx.y, t = threadIdx.x;
  int n0 = ch*128;
  float acc = 0.f;
  for (int r=0;r<128;r++){
    int n = n0 + r;
    float m = mask[b*NN+n];
    acc += s[((long)(b*NN+n))*CC + t] * m;
  }
  atomicAdd(&g_ssum[b*CC+t], acc);
  if (t < 16){
    float a2 = 0.f;
    for (int r=0;r<128;r++){
      int n = n0 + r; float m = mask[b*NN+n];
      if (t < 9)       a2 += Sigma[((long)(b*NN+n))*9 + t] * m;
      else if (t < 12) a2 += mu[(b*NN+n)*3 + (t-9)] * m;
      else if (t < 15){ float v = mu[(b*NN+n)*3 + (t-12)]; a2 += v*v*m; }
      else             a2 += m;
    }
    atomicAdd(&g_initacc[b*16+t], a2);
  }
}

__global__ void finalize_init_k(const float* __restrict__ gW){
  int b = blockIdx.x, t = threadIdx.x;   // 256 threads
  __shared__ float sg[CC];
  __shared__ float sh[32];
  float cnt  = fmaxf(g_initacc[b*16+15], 1e-8f);
  float invc = 1.f/cnt;
  sg[t] = g_ssum[b*CC+t]*invc;
  __syncthreads();
  const float* w = gW + (long)t*CC;
  float acc = 0.f;
#pragma unroll 8
  for (int j=0;j<CC;j++) acc = fmaf(sg[j], w[j], acc);
  float n2 = blockReduceSum(acc*acc, sh);
  g_q[b*CC+t] = acc / fmaxf(sqrtf(n2), 1e-12f);
  if (t < 3){
    float mean = g_initacc[b*16+9+t]*invc;
    float m2v  = g_initacc[b*16+12+t]*invc;
    float var  = m2v - mean*mean;          // exact mask-weighted variance
    g_mean[b*3+t] = mean;
    g_std[b*3+t]  = fmaxf(sqrtf(fmaxf(var, 1e-8f)), 0.03f);
  }
  if (t < 9){
    int r = t/3, c = t%3;
    g_sigavg[b*9+t] = 0.5f*(g_initacc[b*16+t] + g_initacc[b*16 + c*3 + r])*invc;
  }
}

__global__ void geoconst_k(const float* __restrict__ raw, const float* __restrict__ gbias){
  if (threadIdx.x==0){
    float a=0.f, bs=0.f;
    for (int h=0;h<HH;h++){
      float x = raw[h];
      a  += (x > 20.f) ? x : log1pf(__expf(x));
      bs += gbias[h];
    }
    g_geo[0] = a; g_geo[1] = bs;
  }
}

// ---------------- scores: q . l2norm(pool_k) ----------------
__global__ void scores_k(const float* __restrict__ pool){
  int b = blockIdx.y;
  int k = blockIdx.x*8 + (threadIdx.x >> 5);
  int lane = threadIdx.x & 31;
  const float* pr = pool + (long)k*CC;
  const float* qr = g_q + b*CC;
  float dot=0.f, n2=0.f;
  for (int c=lane;c<CC;c+=32){ float p = pr[c]; dot += qr[c]*p; n2 += p*p; }
  dot = warpSum(dot); n2 = warpSum(n2);
  if (lane==0) g_scores[b*KM+k] = dot / fmaxf(sqrtf(n2), 1e-12f);
}

// ---------------- top-k: bitonic sort, descending, tie -> lower index ----------------
__global__ void topk_k(){
  int b = blockIdx.x, t = threadIdx.x;   // 512 threads
  __shared__ float ks[KM];
  __shared__ int   vs[KM];
  for (int i=t;i<KM;i+=512){ ks[i]=g_scores[b*KM+i]; vs[i]=i; }
  for (int size=2; size<=KM; size<<=1){
    for (int stride=size>>1; stride>0; stride>>=1){
      __syncthreads();
      int lo = 2*t - (t & (stride-1));
      int hi = lo + stride;
      bool dirDesc = ((lo & size) == 0);
      float as_=ks[lo], bs_=ks[hi]; int ai=vs[lo], bi=vs[hi];
      bool aBefore = (as_ > bs_) || (as_==bs_ && ai<bi);
      if (dirDesc ? !aBefore : aBefore){
        ks[lo]=bs_; vs[lo]=bi; ks[hi]=as_; vs[hi]=ai;
      }
    }
  }
  __syncthreads();
  if (t < KU) g_idx[b*KU+t] = vs[t];
}

// ---------------- gather slots + init mu_k / Sig_k ----------------
__global__ void gather_init_k(const float* __restrict__ pool, const float* __restrict__ gpool){
  int bk = blockIdx.x;
  int b  = bk / KU;
  int id = g_idx[bk];
  int t  = threadIdx.x;
  g_slots[(long)bk*CC + t] = pool[(long)id*CC + t];
  if (t < 3){
    float off = gpool[id*3+t];
    g_muk[bk*3+t] = g_mean[b*3+t] + off * (0.5f * g_std[b*3+t]);
  }
  if (t < 9){
    float v = g_sigavg[b*9+t]*0.1f;
    if (t==0||t==4||t==8) v += 0.0009f + 1e-6f;   // SIG_FLOOR^2 + JIT
    g_sigk[bk*9+t] = v;
  }
}

// ---------------- generic NT GEMM: C = act(scale*A.B^T [+bias]) [+resid] ----------------
__global__ void gemm_nt(const float* __restrict__ A, const float* __restrict__ B,
                        float* __restrict__ C, int M, int Nc, int K,
                        long sA, long sB, long sC, float scale,
                        const float* __restrict__ bias, int act,
                        const float* __restrict__ resid,
                        const float* __restrict__ rowdiv,
                        const float* __restrict__ gramn)
{
  int z = blockIdx.z;
  const float* Ab = A + (long)z*sA;
  const float* Bb = B + (long)z*sB;
  float* Cb = C + (long)z*sC;
  int m0 = blockIdx.y*64, n0 = blockIdx.x*64;
  __shared__ float As[16][68];
  __shared__ float Bs[16][68];
  int t = threadIdx.x;
  int lr = t>>2, lc = (t&3)*4;
  int ty = t>>4, tx = t&15;
  float acc[4][4];
#pragma unroll
  for (int i=0;i<4;i++)
#pragma unroll
    for (int j=0;j<4;j++) acc[i][j]=0.f;
  for (int k0=0;k0<K;k0+=16){
#pragma unroll
    for (int i=0;i<4;i++){
      int kk = lc+i;
      float v = 0.f;
      if (m0+lr < M && k0+kk < K) v = Ab[(long)(m0+lr)*K + k0+kk];
      As[kk][lr] = v;
      float w = 0.f;
      if (n0+lr < Nc && k0+kk < K) w = Bb[(long)(n0+lr)*K + k0+kk];
      Bs[kk][lr] = w;
    }
    __syncthreads();
#pragma unroll
    for (int kk=0;kk<16;kk++){
      float a0=As[kk][ty*4+0], a1=As[kk][ty*4+1], a2=As[kk][ty*4+2], a3=As[kk][ty*4+3];
      float b0=Bs[kk][tx*4+0], b1=Bs[kk][tx*4+1], b2=Bs[kk][tx*4+2], b3=Bs[kk][tx*4+3];
      acc[0][0]+=a0*b0; acc[0][1]+=a0*b1; acc[0][2]+=a0*b2; acc[0][3]+=a0*b3;
      acc[1][0]+=a1*b0; acc[1][1]+=a1*b1; acc[1][2]+=a1*b2; acc[1][3]+=a1*b3;
      acc[2][0]+=a2*b0; acc[2][1]+=a2*b1; acc[2][2]+=a2*b2; acc[2][3]+=a2*b3;
      acc[3][0]+=a3*b0; acc[3][1]+=a3*b1; acc[3][2]+=a3*b2; acc[3][3]+=a3*b3;
    }
    __syncthreads();
  }
#pragma unroll
  for (int i=0;i<4;i++){
    int m = m0 + ty*4 + i;
    if (m >= M) continue;
    float rd = rowdiv ? 1.f/fmaxf(rowdiv[(long)z*M+m], 1e-8f) : 1.f;
    float gm = gramn ? gramn[(long)z*M+m] : 1.f;
#pragma unroll
    for (int j=0;j<4;j++){
      int n = n0 + tx*4 + j;
      if (n >= Nc) continue;
      float v = acc[i][j]*scale*rd;
      if (bias)  v += bias[n];
      if (act==1) v = 0.5f*v*(1.f + erff(v*0.70710678118654752f));
      if (gramn) v *= gm * gramn[(long)z*M+n];
      if (resid) v += resid[(long)z*sC + (long)m*Nc + n];
      Cb[(long)m*Nc + n] = v;
    }
  }
}

// ---------------- generic NN GEMM: C = scale*A.B  (with per-row divide) ----------------
__global__ void gemm_nn(const float* __restrict__ A, const float* __restrict__ B,
                        float* __restrict__ C, int M, int Nc, int K,
                        long sA, long sB, long sC, float scale,
                        const float* __restrict__ rowdiv)
{
  int z = blockIdx.z;
  const float* Ab = A + (long)z*sA;
  const float* Bb = B + (long)z*sB;
  float* Cb = C + (long)z*sC;
  int m0 = blockIdx.y*64, n0 = blockIdx.x*64;
  __shared__ float As[16][68];
  __shared__ float Bs[16][68];
  int t = threadIdx.x;
  int lr = t>>2, lc = (t&3)*4;
  int brow = t>>6, bcol = t&63;
  int ty = t>>4, tx = t&15;
  float acc[4][4];
#pragma unroll
  for (int i=0;i<4;i++)
#pragma unroll
    for (int j=0;j<4;j++) acc[i][j]=0.f;
  for (int k0=0;k0<K;k0+=16){
#pragma unroll
    for (int i=0;i<4;i++){
      int kk = lc+i;
      float v = 0.f;
      if (m0+lr < M && k0+kk < K) v = Ab[(long)(m0+lr)*K + k0+kk];
      As[kk][lr] = v;
      int kb = brow + i*4;
      float w = 0.f;
      if (k0+kb < K && n0+bcol < Nc) w = Bb[(long)(k0+kb)*Nc + n0+bcol];
      Bs[kb][bcol] = w;
    }
    __syncthreads();
#pragma unroll
    for (int kk=0;kk<16;kk++){
      float a0=As[kk][ty*4+0], a1=As[kk][ty*4+1], a2=As[kk][ty*4+2], a3=As[kk][ty*4+3];
      float b0=Bs[kk][tx*4+0], b1=Bs[kk][tx*4+1], b2=Bs[kk][tx*4+2], b3=Bs[kk][tx*4+3];
      acc[0][0]+=a0*b0; acc[0][1]+=a0*b1; acc[0][2]+=a0*b2; acc[0][3]+=a0*b3;
      acc[1][0]+=a1*b0; acc[1][1]+=a1*b1; acc[1][2]+=a1*b2; acc[1][3]+=a1*b3;
      acc[2][0]+=a2*b0; acc[2][1]+=a2*b1; acc[2][2]+=a2*b2; acc[2][3]+=a2*b3;
      acc[3][0]+=a3*b0; acc[3][1]+=a3*b1; acc[3][2]+=a3*b2; acc[3][3]+=a3*b3;
    }
    __syncthreads();
  }
#pragma unroll
  for (int i=0;i<4;i++){
    int m = m0 + ty*4 + i;
    if (m >= M) continue;
    float rd = rowdiv ? 1.f/fmaxf(rowdiv[(long)z*M+m], 1e-8f) : 1.f;
#pragma unroll
    for (int j=0;j<4;j++){
      int n = n0 + tx*4 + j;
      if (n >= Nc) continue;
      Cb[(long)m*Nc + n] = acc[i][j]*scale*rd;
    }
  }
}

// ---------------- fused geometry + softmax (per (b,n)) ----------------
__global__ void geo_softmax_k(const float* __restrict__ mu, const float* __restrict__ Sigma,
                              const float* __restrict__ mask, const float* __restrict__ w_geo,
                              float* __restrict__ outA){
  int n = blockIdx.x, b = blockIdx.y;
  int t = threadIdx.x;                    // 192 threads
  __shared__ float mun[3], sgn[6];
  __shared__ float sh[32];
  if (t < 3) mun[t] = mu[(b*NN+n)*3 + t];
  if (t < 6){
    const int map[6] = {0,1,2,4,5,8};
    sgn[t] = Sigma[((long)(b*NN+n))*9 + map[t]];
  }
  __syncthreads();
  float m = mask[b*NN+n];
  float logit = -INFINITY;
  if (t < KU){
    int bk = b*KU + t;
    float d0 = mun[0]-g_muk[bk*3+0], d1 = mun[1]-g_muk[bk*3+1], d2 = mun[2]-g_muk[bk*3+2];
    float a  = sgn[0]+g_sigk[bk*9+0];
    float bb = sgn[1]+g_sigk[bk*9+1];
    float c  = sgn[2]+g_sigk[bk*9+2];
    float dd = sgn[3]+g_sigk[bk*9+4];
    float e  = sgn[4]+g_sigk[bk*9+5];
    float f  = sgn[5]+g_sigk[bk*9+8];
    float A00 = dd*f - e*e, A01 = c*e - bb*f, A02 = bb*e - c*dd;
    float A11 = a*f - c*c,  A12 = bb*c - a*e, A22 = a*dd - bb*bb;
    float det = a*A00 + bb*A01 + c*A02;      // SPD -> det > 0
    float inv = 1.f/det;
    float maha = (d0*(A00*d0 + A01*d1 + A02*d2)
                + d1*(A01*d0 + A11*d1 + A12*d2)
                + d2*(A02*d0 + A12*d1 + A22*d2)) * inv;
    float G = -0.5f*(maha + __logf(det));
    float sem = g_logits[((long)(b*NN+n))*KU + t];
    float lg = sem + w_geo[0]*(g_geo[0]*G + g_geo[1]);    // TAU = 1
    logit = (m < 0.5f) ? -1e9f : lg;
  }
  float mx  = blockReduceMax(logit, sh);
  float ex  = (t < KU) ? __expf(logit - mx) : 0.f;
  float sum = blockReduceSum(ex, sh);
  if (t < KU){
    float Av = ex/sum * m;
    outA[((long)(b*NN+n))*KU + t] = Av;
    g_At[((long)(b*KU+t))*NN + n] = Av;
  }
}

// ---------------- EM update (mu_k, Sig_k, occ) per (b,k) ----------------
__global__ void em_update_k(const float* __restrict__ mu, const float* __restrict__ Sigma){
  int bk = blockIdx.x, b = bk/KU, t = threadIdx.x;   // 256 threads
  __shared__ float sh[32];
  float s0=0, s1x=0, s1y=0, s1z=0;
  float sxx=0, sxy=0, sxz=0, syy=0, syz=0, szz=0;
  float q0=0,q1=0,q2=0,q3=0,q4=0,q5=0;
  const float* At = g_At + (long)bk*NN;
  for (int n=t; n<NN; n+=256){
    float a = At[n];
    long b3 = (long)(b*NN+n)*3;
    float mx_=mu[b3], my_=mu[b3+1], mz_=mu[b3+2];
    s0 += a; s1x += a*mx_; s1y += a*my_; s1z += a*mz_;
    sxx += a*mx_*mx_; sxy += a*mx_*my_; sxz += a*mx_*mz_;
    syy += a*my_*my_; syz += a*my_*mz_; szz += a*mz_*mz_;
    long b9 = (long)(b*NN+n)*9;
    q0 += a*Sigma[b9+0]; q1 += a*Sigma[b9+1]; q2 += a*Sigma[b9+2];
    q3 += a*Sigma[b9+4]; q4 += a*Sigma[b9+5]; q5 += a*Sigma[b9+8];
  }
  s0  = blockReduceSum(s0, sh);
  s1x = blockReduceSum(s1x, sh); s1y = blockReduceSum(s1y, sh); s1z = blockReduceSum(s1z, sh);
  sxx = blockReduceSum(sxx, sh); sxy = blockReduceSum(sxy, sh); sxz = blockReduceSum(sxz, sh);
  syy = blockReduceSum(syy, sh); syz = blockReduceSum(syz, sh); szz = blockReduceSum(szz, sh);
  q0 = blockReduceSum(q0, sh); q1 = blockReduceSum(q1, sh); q2 = blockReduceSum(q2, sh);
  q3 = blockReduceSum(q3, sh); q4 = blockReduceSum(q4, sh); q5 = blockReduceSum(q5, sh);
  if (t==0){
    float occ = fmaxf(s0, 1e-8f);
    float inv = 1.f/occ;
    float m0 = s1x*inv, m1_ = s1y*inv, m2_ = s1z*inv;
    g_muk[bk*3+0]=m0; g_muk[bk*3+1]=m1_; g_muk[bk*3+2]=m2_;
    g_occ[bk] = s0;
    // sum_n A*(mu-mu_k)(mu-mu_k)^T = S2 - m s1^T - s1 m^T + s0 m m^T
    float O00 = sxx - 2.f*m0*s1x  + s0*m0*m0;
    float O01 = sxy - m0*s1y - s1x*m1_ + s0*m0*m1_;
    float O02 = sxz - m0*s1z - s1x*m2_ + s0*m0*m2_;
    float O11 = syy - 2.f*m1_*s1y + s0*m1_*m1_;
    float O12 = syz - m1_*s1z - s1y*m2_ + s0*m1_*m2_;
    float O22 = szz - 2.f*m2_*s1z + s0*m2_*m2_;
    float S00 = (q0+O00)*inv, S01 = (q1+O01)*inv, S02 = (q2+O02)*inv;
    float S11 = (q3+O11)*inv, S12 = (q4+O12)*inv, S22 = (q5+O22)*inv;
    // sym + JIT, diag floor, sym + JIT  ->  diag = max(d+1e-6, 9e-4) + 1e-6
    float D00 = fmaxf(S00 + 1e-6f, 0.0009f) + 1e-6f;
    float D11 = fmaxf(S11 + 1e-6f, 0.0009f) + 1e-6f;
    float D22 = fmaxf(S22 + 1e-6f, 0.0009f) + 1e-6f;
    g_sigk[bk*9+0]=D00; g_sigk[bk*9+1]=S01; g_sigk[bk*9+2]=S02;
    g_sigk[bk*9+3]=S01; g_sigk[bk*9+4]=D11; g_sigk[bk*9+5]=S12;
    g_sigk[bk*9+6]=S02; g_sigk[bk*9+7]=S12; g_sigk[bk*9+8]=D22;
  }
}

// ---------------- GRU combine + LayerNorm ----------------
__global__ void gru_ln_k(const float* __restrict__ ln_g, const float* __restrict__ ln_b){
  int bk = blockIdx.x, c = threadIdx.x;   // 256 threads
  __shared__ float sh[32];
  long base = (long)bk*3*CC;
  float gi0 = g_gi[base + c],        gh0 = g_gh[base + c];
  float gi1 = g_gi[base + CC + c],   gh1 = g_gh[base + CC + c];
  float gi2 = g_gi[base + 2*CC + c], gh2 = g_gh[base + 2*CC + c];
  float r  = 1.f/(1.f + __expf(-(gi0+gh0)));
  float z  = 1.f/(1.f + __expf(-(gi1+gh1)));
  float nn_ = tanhf(gi2 + r*gh2);
  float h  = g_slots[(long)bk*CC + c];
  float sn = (1.f - z)*nn_ + z*h;
  g_slots[(long)bk*CC + c] = sn;
  float mean = blockReduceSum(sn, sh) * (1.f/CC);
  float d = sn - mean;
  float var = blockReduceSum(d*d, sh) * (1.f/CC);
  g_xm[(long)bk*CC + c] = d * rsqrtf(var + 1e-5f) * ln_g[c] + ln_b[c];
}

// ---------------- losses ----------------
__global__ void hist_k(){
  __shared__ float hist[KM];
  __shared__ float sh[32];
  int t = threadIdx.x;   // 1024
  hist[t] = 0.f;
  __syncthreads();
  if (t < BK) atomicAdd(&hist[g_idx[t]], 1.f);
  __syncthreads();
  float p  = hist[t] / fmaxf((float)BK, 1.f);
  float pc = fmaxf(p, 1e-8f);
  float lp = logf(pc);
  float kl  = blockReduceSum(pc*(lp + logf((float)KM)), sh);
  float ent = blockReduceSum(pc*lp, sh);
  if (t==0){ g_red[0]=kl; g_red[1]=ent; }
}

__global__ void occ2_k(){
  __shared__ float bsum[BB];
  __shared__ float sh[32];
  int t = threadIdx.x;   // 704
  if (t < BB) bsum[t] = 0.f;
  __syncthreads();
  float o = 0.f; int b = 0;
  if (t < BK){ o = g_occ[t]; b = t/KU; atomicAdd(&bsum[b], o); }
  __syncthreads();
  float v = 0.f;
  if (t < BK){
    float d = o / fmaxf(bsum[b], 1e-8f) - 1.f/(float)KU;
    v = d*d;
  }
  v = blockReduceSum(v, sh);
  if (t==0) g_red[2] = v;
}

__global__ void rownorm_k(){
  int bk = blockIdx.x;   // 256 threads
  __shared__ float sh[32];
  const float* row = g_At + (long)bk*NN;
  float s = 0.f;
  for (int n=threadIdx.x; n<NN; n+=256){ float v = row[n]; s += v*v; }
  s = blockReduceSum(s, sh);
  if (threadIdx.x==0) g_gramn[bk] = 1.f/fmaxf(sqrtf(s), 1e-8f);
}

__global__ void col_reduce_k(){
  long e = (long)blockIdx.x*256 + threadIdx.x;
  float v = 0.f;
  if (e < (long)BB*KU*KU){
    int rem = (int)(e % (KU*KU));
    int r = rem / KU, c = rem % KU;
    if (r != c){ float x = g_R[e]; v = x*x; }
  }
  v = warpSum(v);
  if ((threadIdx.x & 31)==0) atomicAdd(&g_red[3], v);
}

__global__ void final_k(float* __restrict__ out){
  if (threadIdx.x==0){
    float kl = g_red[0], ent = g_red[1];
    float occ_mse = g_red[2] / (float)(BB*KU);
    float col = g_red[3] / (float)((long)BB*KU*KU);
    out[OFF_SCAL+0] = kl;
    out[OFF_SCAL+1] = ent;
    out[OFF_SCAL+2] = occ_mse;
    out[OFF_SCAL+3] = col;
    out[OFF_SCAL+4] = 0.05f*kl + 0.0f*ent + 0.5f*occ_mse + 0.1f*col;
  }
}

__global__ void pack_k(float* __restrict__ out){
  long i = (long)blockIdx.x*256 + threadIdx.x;
  if (i < (long)BK*CC) out[OFF_SLOTS + i] = g_slots[i];
  if (i < BK*3)        out[OFF_MUK + i]   = g_muk[i];
  if (i < BK*9)        out[OFF_SIGK + i]  = g_sigk[i];
  if (i < BK)          out[OFF_IDX + i]   = (float)g_idx[i];
}

// ---------------- launch ----------------
static inline void gnt(const float*A,const float*B,float*C,int M,int Nc,int K,
                       long sA,long sB,long sC,int nz,float scale,
                       const float*bias,int act,const float*resid,
                       const float*rowdiv,const float*gramn){
  dim3 g((Nc+63)/64, (M+63)/64, nz);
  gemm_nt<<<g,256>>>(A,B,C,M,Nc,K,sA,sB,sC,scale,bias,act,resid,rowdiv,gramn);
}

extern "C" void kernel_launch(void* const* d_in, const int* in_sizes, int n_in,
                              void* d_out, int out_size) {
  const float* s      = (const float*)d_in[0];
  const float* mu     = (const float*)d_in[1];
  const float* Sigma  = (const float*)d_in[2];
  const float* mask   = (const float*)d_in[3];
  const float* pool   = (const float*)d_in[4];
  const float* gpool  = (const float*)d_in[5];
  const float* gating_W = (const float*)d_in[6];
  const float* proj_q_W = (const float*)d_in[7];
  const float* proj_k_W = (const float*)d_in[8];
  const float* w_ih   = (const float*)d_in[9];
  const float* w_hh   = (const float*)d_in[10];
  const float* b_ih   = (const float*)d_in[11];
  const float* b_hh   = (const float*)d_in[12];
  const float* ln_g   = (const float*)d_in[13];
  const float* ln_b   = (const float*)d_in[14];
  const float* w1     = (const float*)d_in[15];
  const float* b1     = (const float*)d_in[16];
  const float* w2     = (const float*)d_in[17];
  const float* b2     = (const float*)d_in[18];
  const float* w_geo  = (const float*)d_in[19];
  const float* graw   = (const float*)d_in[20];
  const float* gbias  = (const float*)d_in[21];
  float* out = (float*)d_out;

  float* p_ksem;   cudaGetSymbolAddress((void**)&p_ksem,   g_ksem);
  float* p_qsem;   cudaGetSymbolAddress((void**)&p_qsem,   g_qsem);
  float* p_logits; cudaGetSymbolAddress((void**)&p_logits, g_logits);
  float* p_At;     cudaGetSymbolAddress((void**)&p_At,     g_At);
  float* p_slotin; cudaGetSymbolAddress((void**)&p_slotin, g_slotin);
  float* p_slots;  cudaGetSymbolAddress((void**)&p_slots,  g_slots);
  float* p_gi;     cudaGetSymbolAddress((void**)&p_gi,     g_gi);
  float* p_gh;     cudaGetSymbolAddress((void**)&p_gh,     g_gh);
  float* p_xm;     cudaGetSymbolAddress((void**)&p_xm,     g_xm);
  float* p_t1;     cudaGetSymbolAddress((void**)&p_t1,     g_t1);
  float* p_R;      cudaGetSymbolAddress((void**)&p_R,      g_R);
  float* p_occ;    cudaGetSymbolAddress((void**)&p_occ,    g_occ);
  float* p_gramn;  cudaGetSymbolAddress((void**)&p_gramn,  g_gramn);

  // ---- init ----
  zero_k<<<4,256>>>();
  reduce_init_k<<<dim3(BB, NN/128), 256>>>(s, mu, Sigma, mask);
  finalize_init_k<<<BB,256>>>(gating_W);
  geoconst_k<<<1,32>>>(graw, gbias);
  scores_k<<<dim3(KM/8, BB), 256>>>(pool);
  topk_k<<<BB,512>>>();
  gather_init_k<<<BK,256>>>(pool, gpool);

  // k_sem = s @ proj_k_W^T  (8192x256x256)
  gnt(s, proj_k_W, p_ksem, BB*NN, CC, CC, 0,0,0, 1, 1.f, 0,0,0,0,0);

  for (int it=0; it<3; it++){
    // q_sem = slots @ proj_q_W^T  (684x256x256)
    gnt(p_slots, proj_q_W, p_qsem, BK, CC, CC, 0,0,0, 1, 1.f, 0,0,0,0,0);
    // logits_sem = k_sem @ q_sem^T / 16  (batched over B)
    gnt(p_ksem, p_qsem, p_logits, NN, KU, CC,
        (long)NN*CC, (long)KU*CC, (long)NN*KU, BB, 0.0625f, 0,0,0,0,0);
    // geometry + softmax -> A (to d_out) and A^T (scratch)
    geo_softmax_k<<<dim3(NN, BB), 192>>>(mu, Sigma, mask, w_geo, out);
    // EM update: occ, mu_k, Sig_k
    em_update_k<<<BK,256>>>(mu, Sigma);
    // slot_in = (A^T @ s) / denom   (batched over B; 171x256x2048)
    {
      dim3 g((CC+63)/64, (KU+63)/64, BB);
      gemm_nn<<<g,256>>>(p_At, s, p_slotin, KU, CC, NN,
                         (long)KU*NN, (long)NN*CC, (long)KU*CC, 1.f, p_occ);
    }
    // GRU gates
    gnt(p_slotin, w_ih, p_gi, BK, 3*CC, CC, 0,0,0, 1, 1.f, b_ih, 0, 0,0,0);
    gnt(p_slots,  w_hh, p_gh, BK, 3*CC, CC, 0,0,0, 1, 1.f, b_hh, 0, 0,0,0);
    gru_ln_k<<<BK,256>>>(ln_g, ln_b);
    // MLP
    gnt(p_xm, w1, p_t1, BK, 4*CC, CC,   0,0,0, 1, 1.f, b1, 1, 0,0,0);
    gnt(p_t1, w2, p_slots, BK, CC, 4*CC, 0,0,(long)0, 1, 1.f, b2, 0, p_slots, 0,0);
  }

  // ---- losses ----
  hist_k<<<1,1024>>>();
  occ2_k<<<1,704>>>();
  rownorm_k<<<BK,256>>>();
  gnt(p_At, p_At, p_R, KU, KU, NN,
      (long)KU*NN, (long)KU*NN, (long)KU*KU, BB, 1.f, 0,0,0,0, p_gramn);
  col_reduce_k<<<((long)BB*KU*KU + 255)/256, 256>>>();
  final_k<<<1,32>>>(out);
  pack_k<<<(BK*CC + 255)/256, 256>>>(out);
}

// round 4
// speedup vs baseline: 1.9040x; 1.9040x over previous
#include <cuda_runtime.h>
#include <cuda_bf16.h>
#include <math.h>

// ---------------- problem constants ----------------
#define BB 4
#define NN 2048
#define CC 256
#define KM 1024
#define KU 171            // ceil(2048/12)
#define HH 4
#define BK (BB*KU)        // 684

// ---------------- output layout (float32, tuple flattened) ----------------
#define SZ_A      ((long)BB*NN*KU)            // 1,400,832
#define OFF_SLOTS (SZ_A)
#define OFF_MUK   (OFF_SLOTS + (long)BK*CC)
#define OFF_SIGK  (OFF_MUK   + (long)BK*3)
#define OFF_IDX   (OFF_SIGK  + (long)BK*9)
#define OFF_SCAL  (OFF_IDX   + (long)BK)

// ---------------- scratch (device globals; allocation-free) ----------------
__device__ float g_ssum[BB*CC];
__device__ float g_initacc[BB*16];
__device__ float g_q[BB*CC];
__device__ float g_mean[BB*3];
__device__ float g_std[BB*3];
__device__ float g_sigavg[BB*9];
__device__ float g_scores[BB*KM];
__device__ int   g_idx[BK];
__device__ float g_slots[BK*CC];
__device__ float g_muk[BK*3];
__device__ float g_sigk[BK*9];
__device__ float g_occ[BK];
__device__ float g_ksem[(long)BB*NN*CC];
__device__ float g_qsem[BK*CC];
__device__ float g_logits[(long)BB*NN*KU];
__device__ float g_At[(long)BK*NN];
__device__ float g_slotin[BK*CC];
__device__ float g_xm[BK*CC];
__device__ float g_t1[BK*4*CC];
__device__ float g_R[BB*KU*KU];
__device__ float g_gramn[BK];
__device__ float g_geo[2];
__device__ float g_red[8];
__device__ float g_part[1500000];     // split-K partials (max 1,400,832)
__device__ float g_pgi[2*BK*3*CC];    // gi partials (S=2)
__device__ float g_pgh[2*BK*3*CC];    // gh partials (S=2)

// ---------------- reduction helpers ----------------
__device__ __forceinline__ float warpSum(float v){
#pragma unroll
  for (int o=16;o;o>>=1) v += __shfl_xor_sync(0xffffffffu, v, o);
  return v;
}
__device__ __forceinline__ float warpMax(float v){
#pragma unroll
  for (int o=16;o;o>>=1) v = fmaxf(v, __shfl_xor_sync(0xffffffffu, v, o));
  return v;
}
__device__ __forceinline__ float blockReduceSum(float v, float* sh){
  int lane = threadIdx.x & 31, w = threadIdx.x >> 5;
  v = warpSum(v);
  if (lane==0) sh[w] = v;
  __syncthreads();
  int nw = (blockDim.x + 31) >> 5;
  float x = (threadIdx.x < nw) ? sh[threadIdx.x] : 0.f;
  if (w==0) x = warpSum(x);
  if (threadIdx.x==0) sh[0] = x;
  __syncthreads();
  float r = sh[0];
  __syncthreads();
  return r;
}
__device__ __forceinline__ float blockReduceMax(float v, float* sh){
  int lane = threadIdx.x & 31, w = threadIdx.x >> 5;
  v = warpMax(v);
  if (lane==0) sh[w] = v;
  __syncthreads();
  int nw = (blockDim.x + 31) >> 5;
  float x = (threadIdx.x < nw) ? sh[threadIdx.x] : -INFINITY;
  if (w==0) x = warpMax(x);
  if (threadIdx.x==0) sh[0] = x;
  __syncthreads();
  float r = sh[0];
  __syncthreads();
  return r;
}

// ---------------- zero ----------------
__global__ void zero_k(){
  int i = blockIdx.x*256 + threadIdx.x;
  if (i < BB*CC) g_ssum[i] = 0.f;
  if (i < BB*16) g_initacc[i] = 0.f;
  if (i < 8)     g_red[i] = 0.f;
}

// ---------------- init reductions over N ----------------
__global__ void reduce_init_k(const float* __restrict__ s, const float* __restrict__ mu,
                              const float* __restrict__ Sigma, const float* __restrict__ mask){
  int b = blockIdx.x, ch = blockIdx.y, t = threadIdx.x;
  int n0 = ch*128;
  float acc = 0.f;
  for (int r=0;r<128;r++){
    int n = n0 + r;
    float m = mask[b*NN+n];
    acc += s[((long)(b*NN+n))*CC + t] * m;
  }
  atomicAdd(&g_ssum[b*CC+t], acc);
  if (t < 16){
    float a2 = 0.f;
    for (int r=0;r<128;r++){
      int n = n0 + r; float m = mask[b*NN+n];
      if (t < 9)       a2 += Sigma[((long)(b*NN+n))*9 + t] * m;
      else if (t < 12) a2 += mu[(b*NN+n)*3 + (t-9)] * m;
      else if (t < 15){ float v = mu[(b*NN+n)*3 + (t-12)]; a2 += v*v*m; }
      else             a2 += m;
    }
    atomicAdd(&g_initacc[b*16+t], a2);
  }
}

__global__ void finalize_init_k(const float* __restrict__ gW){
  int b = blockIdx.x, t = threadIdx.x;   // 256 threads
  __shared__ float sg[CC];
  __shared__ float sh[32];
  float cnt  = fmaxf(g_initacc[b*16+15], 1e-8f);
  float invc = 1.f/cnt;
  sg[t] = g_ssum[b*CC+t]*invc;
  __syncthreads();
  const float* w = gW + (long)t*CC;
  float acc = 0.f;
#pragma unroll 8
  for (int j=0;j<CC;j++) acc = fmaf(sg[j], w[j], acc);
  float n2 = blockReduceSum(acc*acc, sh);
  g_q[b*CC+t] = acc / fmaxf(sqrtf(n2), 1e-12f);
  if (t < 3){
    float mean = g_initacc[b*16+9+t]*invc;
    float m2v  = g_initacc[b*16+12+t]*invc;
    float var  = m2v - mean*mean;
    g_mean[b*3+t] = mean;
    g_std[b*3+t]  = fmaxf(sqrtf(fmaxf(var, 1e-8f)), 0.03f);
  }
  if (t < 9){
    int r = t/3, c = t%3;
    g_sigavg[b*9+t] = 0.5f*(g_initacc[b*16+t] + g_initacc[b*16 + c*3 + r])*invc;
  }
}

__global__ void geoconst_k(const float* __restrict__ raw, const float* __restrict__ gbias){
  if (threadIdx.x==0){
    float a=0.f, bs=0.f;
    for (int h=0;h<HH;h++){
      float x = raw[h];
      a  += (x > 20.f) ? x : log1pf(__expf(x));
      bs += gbias[h];
    }
    g_geo[0] = a; g_geo[1] = bs;
  }
}

// ---------------- scores ----------------
__global__ void scores_k(const float* __restrict__ pool){
  int b = blockIdx.y;
  int k = blockIdx.x*8 + (threadIdx.x >> 5);
  int lane = threadIdx.x & 31;
  const float* pr = pool + (long)k*CC;
  const float* qr = g_q + b*CC;
  float dot=0.f, n2=0.f;
  for (int c=lane;c<CC;c+=32){ float p = pr[c]; dot += qr[c]*p; n2 += p*p; }
  dot = warpSum(dot); n2 = warpSum(n2);
  if (lane==0) g_scores[b*KM+k] = dot / fmaxf(sqrtf(n2), 1e-12f);
}

// ---------------- top-k bitonic ----------------
__global__ void topk_k(){
  int b = blockIdx.x, t = threadIdx.x;   // 512 threads
  __shared__ float ks[KM];
  __shared__ int   vs[KM];
  for (int i=t;i<KM;i+=512){ ks[i]=g_scores[b*KM+i]; vs[i]=i; }
  for (int size=2; size<=KM; size<<=1){
    for (int stride=size>>1; stride>0; stride>>=1){
      __syncthreads();
      int lo = 2*t - (t & (stride-1));
      int hi = lo + stride;
      bool dirDesc = ((lo & size) == 0);
      float as_=ks[lo], bs_=ks[hi]; int ai=vs[lo], bi=vs[hi];
      bool aBefore = (as_ > bs_) || (as_==bs_ && ai<bi);
      if (dirDesc ? !aBefore : aBefore){
        ks[lo]=bs_; vs[lo]=bi; ks[hi]=as_; vs[hi]=ai;
      }
    }
  }
  __syncthreads();
  if (t < KU) g_idx[b*KU+t] = vs[t];
}

// ---------------- gather + init ----------------
__global__ void gather_init_k(const float* __restrict__ pool, const float* __restrict__ gpool){
  int bk = blockIdx.x;
  int b  = bk / KU;
  int id = g_idx[bk];
  int t  = threadIdx.x;
  g_slots[(long)bk*CC + t] = pool[(long)id*CC + t];
  if (t < 3){
    float off = gpool[id*3+t];
    g_muk[bk*3+t] = g_mean[b*3+t] + off * (0.5f * g_std[b*3+t]);
  }
  if (t < 9){
    float v = g_sigavg[b*9+t]*0.1f;
    if (t==0||t==4||t==8) v += 0.0009f + 1e-6f;
    g_sigk[bk*9+t] = v;
  }
}

// ================= high-throughput GEMM: 128x64x16 tile, 8x4 micro =================
// NNMODE=0: C[m,n] = scale * sum_k A[m,k]*B[n,k]   (NT)
// NNMODE=1: C[m,n] = scale * sum_k A[m,k]*B[k,n]   (NN)
// If S>1: writes partials P[(s*nz+z)*M*N + m*N + n] (scale still applied).
template<int NNMODE>
__global__ void __launch_bounds__(256)
gemm8x4(const float* __restrict__ A, const float* __restrict__ B,
        float* __restrict__ Cd, float* __restrict__ P,
        int M, int N, int K, int lda, int ldb,
        long sA, long sB, long sC,
        int nz, int S, int Kc, float scale)
{
  __shared__ __align__(16) float As[16][132];
  __shared__ __align__(16) float Bs[16][72];
  int zz = blockIdx.z;
  int z = zz % nz, sp = zz / nz;
  const float* Ab = A + (long)z*sA;
  const float* Bb = B + (long)z*sB;
  int m0 = blockIdx.y*128, n0 = blockIdx.x*64;
  int k0 = sp*Kc, kend = min(K, k0+Kc);
  int t = threadIdx.x;
  int tx = t & 15, ty = t >> 4;
  float acc[8][4];
#pragma unroll
  for (int i=0;i<8;i++)
#pragma unroll
    for (int j=0;j<4;j++) acc[i][j]=0.f;

  for (; k0 < kend; k0 += 16){
    // A tile: 128 rows x 16 k, store k-major
#pragma unroll
    for (int i=0;i<2;i++){
      int f = t + 256*i;
      int r = f >> 2, c4 = f & 3;
      float4 v = make_float4(0.f,0.f,0.f,0.f);
      if (m0 + r < M) v = *(const float4*)(Ab + (long)(m0+r)*lda + k0 + c4*4);
      As[c4*4+0][r]=v.x; As[c4*4+1][r]=v.y; As[c4*4+2][r]=v.z; As[c4*4+3][r]=v.w;
    }
    if (NNMODE){
      // B tile: 16 k-rows x 64 n, already k-major
      int rk = t >> 4, c4 = t & 15;
      float4 v = make_float4(0.f,0.f,0.f,0.f);
      if (n0 + c4*4 < N) v = *(const float4*)(Bb + (long)(k0+rk)*ldb + n0 + c4*4);
      *(float4*)&Bs[rk][c4*4] = v;
    } else {
      // B tile: 64 n-rows x 16 k, transpose to k-major
      int r = t >> 2, c4 = t & 3;
      float4 v = make_float4(0.f,0.f,0.f,0.f);
      if (n0 + r < N) v = *(const float4*)(Bb + (long)(n0+r)*ldb + k0 + c4*4);
      Bs[c4*4+0][r]=v.x; Bs[c4*4+1][r]=v.y; Bs[c4*4+2][r]=v.z; Bs[c4*4+3][r]=v.w;
    }
    __syncthreads();
#pragma unroll
    for (int kk=0;kk<16;kk++){
      float4 b4 = *(float4*)&Bs[kk][tx*4];
      float4 a0 = *(float4*)&As[kk][ty*8];
      float4 a1 = *(float4*)&As[kk][ty*8+4];
      float av0=a0.x, av1=a0.y, av2=a0.z, av3=a0.w;
      float av4=a1.x, av5=a1.y, av6=a1.z, av7=a1.w;
      acc[0][0]=fmaf(av0,b4.x,acc[0][0]); acc[0][1]=fmaf(av0,b4.y,acc[0][1]); acc[0][2]=fmaf(av0,b4.z,acc[0][2]); acc[0][3]=fmaf(av0,b4.w,acc[0][3]);
      acc[1][0]=fmaf(av1,b4.x,acc[1][0]); acc[1][1]=fmaf(av1,b4.y,acc[1][1]); acc[1][2]=fmaf(av1,b4.z,acc[1][2]); acc[1][3]=fmaf(av1,b4.w,acc[1][3]);
      acc[2][0]=fmaf(av2,b4.x,acc[2][0]); acc[2][1]=fmaf(av2,b4.y,acc[2][1]); acc[2][2]=fmaf(av2,b4.z,acc[2][2]); acc[2][3]=fmaf(av2,b4.w,acc[2][3]);
      acc[3][0]=fmaf(av3,b4.x,acc[3][0]); acc[3][1]=fmaf(av3,b4.y,acc[3][1]); acc[3][2]=fmaf(av3,b4.z,acc[3][2]); acc[3][3]=fmaf(av3,b4.w,acc[3][3]);
      acc[4][0]=fmaf(av4,b4.x,acc[4][0]); acc[4][1]=fmaf(av4,b4.y,acc[4][1]); acc[4][2]=fmaf(av4,b4.z,acc[4][2]); acc[4][3]=fmaf(av4,b4.w,acc[4][3]);
      acc[5][0]=fmaf(av5,b4.x,acc[5][0]); acc[5][1]=fmaf(av5,b4.y,acc[5][1]); acc[5][2]=fmaf(av5,b4.z,acc[5][2]); acc[5][3]=fmaf(av5,b4.w,acc[5][3]);
      acc[6][0]=fmaf(av6,b4.x,acc[6][0]); acc[6][1]=fmaf(av6,b4.y,acc[6][1]); acc[6][2]=fmaf(av6,b4.z,acc[6][2]); acc[6][3]=fmaf(av6,b4.w,acc[6][3]);
      acc[7][0]=fmaf(av7,b4.x,acc[7][0]); acc[7][1]=fmaf(av7,b4.y,acc[7][1]); acc[7][2]=fmaf(av7,b4.z,acc[7][2]); acc[7][3]=fmaf(av7,b4.w,acc[7][3]);
    }
    __syncthreads();
  }

  long MN = (long)M*N;
  float* outp = (S>1) ? (P + (long)(sp*nz+z)*MN) : (Cd + (long)z*sC);
#pragma unroll
  for (int i=0;i<8;i++){
    int m = m0 + ty*8 + i;
    if (m >= M) continue;
#pragma unroll
    for (int j=0;j<4;j++){
      int n = n0 + tx*4 + j;
      if (n >= N) continue;
      outp[(long)m*N + n] = acc[i][j]*scale;
    }
  }
}

// ---------------- split-K reduce + epilogue ----------------
__global__ void reduce_epi(const float* __restrict__ P, float* __restrict__ C,
                           int M, int N, int nz, int S,
                           const float* __restrict__ bias, int act,
                           const float* __restrict__ resid,
                           const float* __restrict__ rowdiv,
                           const float* __restrict__ gramn)
{
  long MN = (long)M*N;
  long total = (long)nz*MN;
  long e = (long)blockIdx.x*256 + threadIdx.x;
  if (e >= total) return;
  int z = (int)(e / MN); long rem = e - (long)z*MN;
  int m = (int)(rem / N), n = (int)(rem - (long)m*N);
  float v = 0.f;
  for (int s=0;s<S;s++) v += P[(long)(s*nz+z)*MN + rem];
  if (rowdiv) v *= 1.f/fmaxf(rowdiv[z*M+m], 1e-8f);
  if (bias)   v += bias[n];
  if (act)    v = 0.5f*v*(1.f + erff(v*0.70710678118654752f));
  if (gramn)  v *= gramn[z*M+m]*gramn[z*M+n];
  if (resid)  v += resid[e];
  C[e] = v;
}

// ---------------- fused geometry + softmax ----------------
__global__ void geo_softmax_k(const float* __restrict__ mu, const float* __restrict__ Sigma,
                              const float* __restrict__ mask, const float* __restrict__ w_geo,
                              float* __restrict__ outA){
  int n = blockIdx.x, b = blockIdx.y;
  int t = threadIdx.x;                    // 192 threads
  __shared__ float mun[3], sgn[6];
  __shared__ float sh[32];
  if (t < 3) mun[t] = mu[(b*NN+n)*3 + t];
  if (t < 6){
    const int map[6] = {0,1,2,4,5,8};
    sgn[t] = Sigma[((long)(b*NN+n))*9 + map[t]];
  }
  __syncthreads();
  float m = mask[b*NN+n];
  float logit = -INFINITY;
  if (t < KU){
    int bk = b*KU + t;
    float d0 = mun[0]-g_muk[bk*3+0], d1 = mun[1]-g_muk[bk*3+1], d2 = mun[2]-g_muk[bk*3+2];
    float a  = sgn[0]+g_sigk[bk*9+0];
    float bb = sgn[1]+g_sigk[bk*9+1];
    float c  = sgn[2]+g_sigk[bk*9+2];
    float dd = sgn[3]+g_sigk[bk*9+4];
    float e  = sgn[4]+g_sigk[bk*9+5];
    float f  = sgn[5]+g_sigk[bk*9+8];
    float A00 = dd*f - e*e, A01 = c*e - bb*f, A02 = bb*e - c*dd;
    float A11 = a*f - c*c,  A12 = bb*c - a*e, A22 = a*dd - bb*bb;
    float det = a*A00 + bb*A01 + c*A02;
    float inv = 1.f/det;
    float maha = (d0*(A00*d0 + A01*d1 + A02*d2)
                + d1*(A01*d0 + A11*d1 + A12*d2)
                + d2*(A02*d0 + A12*d1 + A22*d2)) * inv;
    float G = -0.5f*(maha + __logf(det));
    float sem = g_logits[((long)(b*NN+n))*KU + t];
    float lg = sem + w_geo[0]*(g_geo[0]*G + g_geo[1]);
    logit = (m < 0.5f) ? -1e9f : lg;
  }
  float mx  = blockReduceMax(logit, sh);
  float ex  = (t < KU) ? __expf(logit - mx) : 0.f;
  float sum = blockReduceSum(ex, sh);
  if (t < KU){
    float Av = ex/sum * m;
    outA[((long)(b*NN+n))*KU + t] = Av;
    g_At[((long)(b*KU+t))*NN + n] = Av;
  }
}

// ---------------- EM update ----------------
__global__ void em_update_k(const float* __restrict__ mu, const float* __restrict__ Sigma){
  int bk = blockIdx.x, b = bk/KU, t = threadIdx.x;   // 256 threads
  __shared__ float sh[32];
  float s0=0, s1x=0, s1y=0, s1z=0;
  float sxx=0, sxy=0, sxz=0, syy=0, syz=0, szz=0;
  float q0=0,q1=0,q2=0,q3=0,q4=0,q5=0;
  const float* At = g_At + (long)bk*NN;
  for (int n=t; n<NN; n+=256){
    float a = At[n];
    long b3 = (long)(b*NN+n)*3;
    float mx_=mu[b3], my_=mu[b3+1], mz_=mu[b3+2];
    s0 += a; s1x += a*mx_; s1y += a*my_; s1z += a*mz_;
    sxx += a*mx_*mx_; sxy += a*mx_*my_; sxz += a*mx_*mz_;
    syy += a*my_*my_; syz += a*my_*mz_; szz += a*mz_*mz_;
    long b9 = (long)(b*NN+n)*9;
    q0 += a*Sigma[b9+0]; q1 += a*Sigma[b9+1]; q2 += a*Sigma[b9+2];
    q3 += a*Sigma[b9+4]; q4 += a*Sigma[b9+5]; q5 += a*Sigma[b9+8];
  }
  s0  = blockReduceSum(s0, sh);
  s1x = blockReduceSum(s1x, sh); s1y = blockReduceSum(s1y, sh); s1z = blockReduceSum(s1z, sh);
  sxx = blockReduceSum(sxx, sh); sxy = blockReduceSum(sxy, sh); sxz = blockReduceSum(sxz, sh);
  syy = blockReduceSum(syy, sh); syz = blockReduceSum(syz, sh); szz = blockReduceSum(szz, sh);
  q0 = blockReduceSum(q0, sh); q1 = blockReduceSum(q1, sh); q2 = blockReduceSum(q2, sh);
  q3 = blockReduceSum(q3, sh); q4 = blockReduceSum(q4, sh); q5 = blockReduceSum(q5, sh);
  if (t==0){
    float occ = fmaxf(s0, 1e-8f);
    float inv = 1.f/occ;
    float m0 = s1x*inv, m1_ = s1y*inv, m2_ = s1z*inv;
    g_muk[bk*3+0]=m0; g_muk[bk*3+1]=m1_; g_muk[bk*3+2]=m2_;
    g_occ[bk] = s0;
    float O00 = sxx - 2.f*m0*s1x  + s0*m0*m0;
    float O01 = sxy - m0*s1y - s1x*m1_ + s0*m0*m1_;
    float O02 = sxz - m0*s1z - s1x*m2_ + s0*m0*m2_;
    float O11 = syy - 2.f*m1_*s1y + s0*m1_*m1_;
    float O12 = syz - m1_*s1z - s1y*m2_ + s0*m1_*m2_;
    float O22 = szz - 2.f*m2_*s1z + s0*m2_*m2_;
    float S00 = (q0+O00)*inv, S01 = (q1+O01)*inv, S02 = (q2+O02)*inv;
    float S11 = (q3+O11)*inv, S12 = (q4+O12)*inv, S22 = (q5+O22)*inv;
    float D00 = fmaxf(S00 + 1e-6f, 0.0009f) + 1e-6f;
    float D11 = fmaxf(S11 + 1e-6f, 0.0009f) + 1e-6f;
    float D22 = fmaxf(S22 + 1e-6f, 0.0009f) + 1e-6f;
    g_sigk[bk*9+0]=D00; g_sigk[bk*9+1]=S01; g_sigk[bk*9+2]=S02;
    g_sigk[bk*9+3]=S01; g_sigk[bk*9+4]=D11; g_sigk[bk*9+5]=S12;
    g_sigk[bk*9+6]=S02; g_sigk[bk*9+7]=S12; g_sigk[bk*9+8]=D22;
  }
}

// ---------------- fused gi/gh split-K reduce + bias + GRU + LayerNorm ----------------
__global__ void gru_ln_k(const float* __restrict__ b_ih, const float* __restrict__ b_hh,
                         const float* __restrict__ ln_g, const float* __restrict__ ln_b){
  int bk = blockIdx.x, c = threadIdx.x;   // 256 threads
  __shared__ float sh[32];
  const long MN = (long)BK*3*CC;
  long row = (long)bk*3*CC;
  float gi0 = g_pgi[row + c]        + g_pgi[MN + row + c]        + b_ih[c];
  float gi1 = g_pgi[row + CC + c]   + g_pgi[MN + row + CC + c]   + b_ih[CC + c];
  float gi2 = g_pgi[row + 2*CC + c] + g_pgi[MN + row + 2*CC + c] + b_ih[2*CC + c];
  float gh0 = g_pgh[row + c]        + g_pgh[MN + row + c]        + b_hh[c];
  float gh1 = g_pgh[row + CC + c]   + g_pgh[MN + row + CC + c]   + b_hh[CC + c];
  float gh2 = g_pgh[row + 2*CC + c] + g_pgh[MN + row + 2*CC + c] + b_hh[2*CC + c];
  float r  = 1.f/(1.f + __expf(-(gi0+gh0)));
  float z  = 1.f/(1.f + __expf(-(gi1+gh1)));
  float nn_ = tanhf(gi2 + r*gh2);
  float h  = g_slots[(long)bk*CC + c];
  float sn = (1.f - z)*nn_ + z*h;
  g_slots[(long)bk*CC + c] = sn;
  float mean = blockReduceSum(sn, sh) * (1.f/CC);
  float d = sn - mean;
  float var = blockReduceSum(d*d, sh) * (1.f/CC);
  g_xm[(long)bk*CC + c] = d * rsqrtf(var + 1e-5f) * ln_g[c] + ln_b[c];
}

// ---------------- losses ----------------
__global__ void hist_k(){
  __shared__ float hist[KM];
  __shared__ float sh[32];
  int t = threadIdx.x;   // 1024
  hist[t] = 0.f;
  __syncthreads();
  if (t < BK) atomicAdd(&hist[g_idx[t]], 1.f);
  __syncthreads();
  float p  = hist[t] / fmaxf((float)BK, 1.f);
  float pc = fmaxf(p, 1e-8f);
  float lp = logf(pc);
  float kl  = blockReduceSum(pc*(lp + logf((float)KM)), sh);
  float ent = blockReduceSum(pc*lp, sh);
  if (t==0){ g_red[0]=kl; g_red[1]=ent; }
}

__global__ void occ2_k(){
  __shared__ float bsum[BB];
  __shared__ float sh[32];
  int t = threadIdx.x;   // 704
  if (t < BB) bsum[t] = 0.f;
  __syncthreads();
  float o = 0.f; int b = 0;
  if (t < BK){ o = g_occ[t]; b = t/KU; atomicAdd(&bsum[b], o); }
  __syncthreads();
  float v = 0.f;
  if (t < BK){
    float d = o / fmaxf(bsum[b], 1e-8f) - 1.f/(float)KU;
    v = d*d;
  }
  v = blockReduceSum(v, sh);
  if (t==0) g_red[2] = v;
}

__global__ void rownorm_k(){
  int bk = blockIdx.x;   // 256 threads
  __shared__ float sh[32];
  const float* row = g_At + (long)bk*NN;
  float s = 0.f;
  for (int n=threadIdx.x; n<NN; n+=256){ float v = row[n]; s += v*v; }
  s = blockReduceSum(s, sh);
  if (threadIdx.x==0) g_gramn[bk] = 1.f/fmaxf(sqrtf(s), 1e-8f);
}

__global__ void col_reduce_k(){
  long e = (long)blockIdx.x*256 + threadIdx.x;
  float v = 0.f;
  if (e < (long)BB*KU*KU){
    int rem = (int)(e % (KU*KU));
    int r = rem / KU, c = rem % KU;
    if (r != c){ float x = g_R[e]; v = x*x; }
  }
  v = warpSum(v);
  if ((threadIdx.x & 31)==0) atomicAdd(&g_red[3], v);
}

__global__ void final_k(float* __restrict__ out){
  if (threadIdx.x==0){
    float kl = g_red[0], ent = g_red[1];
    float occ_mse = g_red[2] / (float)(BB*KU);
    float col = g_red[3] / (float)((long)BB*KU*KU);
    out[OFF_SCAL+0] = kl;
    out[OFF_SCAL+1] = ent;
    out[OFF_SCAL+2] = occ_mse;
    out[OFF_SCAL+3] = col;
    out[OFF_SCAL+4] = 0.05f*kl + 0.0f*ent + 0.5f*occ_mse + 0.1f*col;
  }
}

__global__ void pack_k(float* __restrict__ out){
  long i = (long)blockIdx.x*256 + threadIdx.x;
  if (i < (long)BK*CC) out[OFF_SLOTS + i] = g_slots[i];
  if (i < BK*3)        out[OFF_MUK + i]   = g_muk[i];
  if (i < BK*9)        out[OFF_SIGK + i]  = g_sigk[i];
  if (i < BK)          out[OFF_IDX + i]   = (float)g_idx[i];
}

// ---------------- host-side wrappers ----------------
static inline void g_nt(const float*A,const float*B,float*C,float*P,
                        int M,int N,int K,int lda,int ldb,
                        long sA,long sB,long sC,int nz,int S,float scale){
  dim3 g((N+63)/64, (M+127)/128, nz*S);
  gemm8x4<0><<<g,256>>>(A,B,C,P,M,N,K,lda,ldb,sA,sB,sC,nz,S,K/S,scale);
}
static inline void g_nn(const float*A,const float*B,float*C,float*P,
                        int M,int N,int K,int lda,int ldb,
                        long sA,long sB,long sC,int nz,int S,float scale){
  dim3 g((N+63)/64, (M+127)/128, nz*S);
  gemm8x4<1><<<g,256>>>(A,B,C,P,M,N,K,lda,ldb,sA,sB,sC,nz,S,K/S,scale);
}
static inline void r_epi(const float*P,float*C,int M,int N,int nz,int S,
                         const float*bias,int act,const float*resid,
                         const float*rowdiv,const float*gramn){
  long total = (long)nz*M*N;
  reduce_epi<<<(unsigned)((total+255)/256),256>>>(P,C,M,N,nz,S,bias,act,resid,rowdiv,gramn);
}

extern "C" void kernel_launch(void* const* d_in, const int* in_sizes, int n_in,
                              void* d_out, int out_size) {
  const float* s      = (const float*)d_in[0];
  const float* mu     = (const float*)d_in[1];
  const float* Sigma  = (const float*)d_in[2];
  const float* mask   = (const float*)d_in[3];
  const float* pool   = (const float*)d_in[4];
  const float* gpool  = (const float*)d_in[5];
  const float* gating_W = (const float*)d_in[6];
  const float* proj_q_W = (const float*)d_in[7];
  const float* proj_k_W = (const float*)d_in[8];
  const float* w_ih   = (const float*)d_in[9];
  const float* w_hh   = (const float*)d_in[10];
  const float* b_ih   = (const float*)d_in[11];
  const float* b_hh   = (const float*)d_in[12];
  const float* ln_g   = (const float*)d_in[13];
  const float* ln_b   = (const float*)d_in[14];
  const float* w1     = (const float*)d_in[15];
  const float* b1     = (const float*)d_in[16];
  const float* w2     = (const float*)d_in[17];
  const float* b2     = (const float*)d_in[18];
  const float* w_geo  = (const float*)d_in[19];
  const float* graw   = (const float*)d_in[20];
  const float* gbias  = (const float*)d_in[21];
  float* out = (float*)d_out;

  float* p_ksem;   cudaGetSymbolAddress((void**)&p_ksem,   g_ksem);
  float* p_qsem;   cudaGetSymbolAddress((void**)&p_qsem,   g_qsem);
  float* p_logits; cudaGetSymbolAddress((void**)&p_logits, g_logits);
  float* p_At;     cudaGetSymbolAddress((void**)&p_At,     g_At);
  float* p_slotin; cudaGetSymbolAddress((void**)&p_slotin, g_slotin);
  float* p_slots;  cudaGetSymbolAddress((void**)&p_slots,  g_slots);
  float* p_xm;     cudaGetSymbolAddress((void**)&p_xm,     g_xm);
  float* p_t1;     cudaGetSymbolAddress((void**)&p_t1,     g_t1);
  float* p_R;      cudaGetSymbolAddress((void**)&p_R,      g_R);
  float* p_occ;    cudaGetSymbolAddress((void**)&p_occ,    g_occ);
  float* p_gramn;  cudaGetSymbolAddress((void**)&p_gramn,  g_gramn);
  float* p_part;   cudaGetSymbolAddress((void**)&p_part,   g_part);
  float* p_pgi;    cudaGetSymbolAddress((void**)&p_pgi,    g_pgi);
  float* p_pgh;    cudaGetSymbolAddress((void**)&p_pgh,    g_pgh);

  // ---- init ----
  zero_k<<<4,256>>>();
  reduce_init_k<<<dim3(BB, NN/128), 256>>>(s, mu, Sigma, mask);
  finalize_init_k<<<BB,256>>>(gating_W);
  geoconst_k<<<1,32>>>(graw, gbias);
  scores_k<<<dim3(KM/8, BB), 256>>>(pool);
  topk_k<<<BB,512>>>();
  gather_init_k<<<BK,256>>>(pool, gpool);

  // k_sem = s @ proj_k_W^T   (8192 x 256 x 256)
  g_nt(s, proj_k_W, p_ksem, p_part, BB*NN, CC, CC, CC, CC, 0,0,0, 1, 1, 1.f);

  for (int it=0; it<3; it++){
    // q_sem = slots @ proj_q_W^T  (684 x 256 x 256), split-K 4
    g_nt(p_slots, proj_q_W, 0, p_part, BK, CC, CC, CC, CC, 0,0,0, 1, 4, 1.f);
    r_epi(p_part, p_qsem, BK, CC, 1, 4, 0,0,0,0,0);
    // logits_sem = k_sem @ q_sem^T / 16   (z=4: 2048 x 171 x 256)
    g_nt(p_ksem, p_qsem, p_logits, 0, NN, KU, CC, CC, CC,
         (long)NN*CC, (long)KU*CC, (long)NN*KU, BB, 1, 0.0625f);
    // geometry + softmax -> A (to d_out) and A^T
    geo_softmax_k<<<dim3(NN, BB), 192>>>(mu, Sigma, mask, w_geo, out);
    // EM update
    em_update_k<<<BK,256>>>(mu, Sigma);
    // slot_in = (A^T @ s) / occ  (z=4: 171 x 256 x 2048), NN-form, split-K 8
    g_nn(p_At, s, 0, p_part, KU, CC, NN, NN, CC,
         (long)KU*NN, (long)NN*CC, 0, BB, 8, 1.f);
    r_epi(p_part, p_slotin, KU, CC, BB, 8, 0,0,0, p_occ, 0);
    // GRU gates (split-K 2 each, fused reduce in gru_ln_k)
    g_nt(p_slotin, w_ih, 0, p_pgi, BK, 3*CC, CC, CC, CC, 0,0,0, 1, 2, 1.f);
    g_nt(p_slots,  w_hh, 0, p_pgh, BK, 3*CC, CC, CC, CC, 0,0,0, 1, 2, 1.f);
    gru_ln_k<<<BK,256>>>(b_ih, b_hh, ln_g, ln_b);
    // MLP
    g_nt(p_xm, w1, 0, p_part, BK, 4*CC, CC, CC, CC, 0,0,0, 1, 2, 1.f);
    r_epi(p_part, p_t1, BK, 4*CC, 1, 2, b1, 1, 0,0,0);
    g_nt(p_t1, w2, 0, p_part, BK, CC, 4*CC, 4*CC, 4*CC, 0,0,0, 1, 4, 1.f);
    r_epi(p_part, p_slots, BK, CC, 1, 4, b2, 0, p_slots, 0,0);
  }

  // ---- losses ----
  hist_k<<<1,1024>>>();
  occ2_k<<<1,704>>>();
  rownorm_k<<<BK,256>>>();
  // Gram = (At . At^T) normalized  (z=4: 171 x 171 x 2048), split-K 8
  g_nt(p_At, p_At, 0, p_part, KU, KU, NN, NN, NN,
       (long)KU*NN, (long)KU*NN, 0, BB, 8, 1.f);
  r_epi(p_part, p_R, KU, KU, BB, 8, 0,0,0,0, p_gramn);
  col_reduce_k<<<(unsigned)(((long)BB*KU*KU + 255)/256), 256>>>();
  final_k<<<1,32>>>(out);
  pack_k<<<(BK*CC + 255)/256, 256>>>(out);
}